// round 16
// baseline (speedup 1.0000x reference)
#include <cuda_runtime.h>
#include <cstdint>

#define B 64
#define NPRED 25200          // 3*(6400+1600+400) anchors*cells
#define TOPK 1024
#define MAXDET 300
#define CONF_THRES 0.25f
#define IOU_THRES 0.45f
#define NBINS 1024
#define CAP 4096             // smem candidate buffer (keys >= bin threshold)

// valid scores lie in (0.25, 1): fp32 bits in (0x3E800000, 0x3F800000)
#define BIN_BASE 0x3E800000u

__device__ unsigned long long g_keys[B * NPRED];   // (score_bits<<32)|(~idx)
__device__ unsigned int       g_hist[B * NBINS];   // zero-init; re-zeroed by K2 tail

// candidate data (decoded boxes for the 1024 selected per image)
__device__ float4 g_box[B * TOPK];                 // x1,y1,x2,y2
__device__ float  g_bar[B * TOPK];
__device__ float  g_bsc[B * TOPK];
__device__ float  g_bcl[B * TOPK];
__device__ unsigned g_active[B * 32];

// suppression bitmatrix, WORD-MAJOR: g_mask[b][w][i] bit jj -> row i suppresses
// j = w*32+jj (j>i bits only). Words w < i/32 are never written (stay 0) and
// never contribute (predicated out).
__device__ unsigned g_mask[B * 32 * TOPK];         // 8.4 MB

__device__ __forceinline__ float sigmoidf(float x) {
    return 1.0f / (1.0f + expf(-x));
}

// ---------------------------------------------------------------------------
// K1: per-candidate score -> sortable key + score-bin histogram
// ---------------------------------------------------------------------------
__device__ __forceinline__ void score_one(const float* __restrict__ r0,
                                          const float* __restrict__ r1,
                                          const float* __restrict__ r2,
                                          int b, int p, bool live)
{
    int pc = p < NPRED ? p : NPRED - 1;
    const float* v;
    if (pc < 19200)      v = r0 + (size_t)(b * 19200 + pc) * 20;
    else if (pc < 24000) v = r1 + (size_t)(b * 4800 + (pc - 19200)) * 20;
    else                 v = r2 + (size_t)(b * 1200 + (pc - 24000)) * 20;

    const float4* v4 = (const float4*)v;
    float4 qa = v4[1];   // obj, cls0..2
    float4 qb = v4[2];
    float4 qc = v4[3];
    float4 qd = v4[4];

    float m = qa.y;
    m = fmaxf(m, qa.z); m = fmaxf(m, qa.w);
    m = fmaxf(m, qb.x); m = fmaxf(m, qb.y); m = fmaxf(m, qb.z); m = fmaxf(m, qb.w);
    m = fmaxf(m, qc.x); m = fmaxf(m, qc.y); m = fmaxf(m, qc.z); m = fmaxf(m, qc.w);
    m = fmaxf(m, qd.x); m = fmaxf(m, qd.y); m = fmaxf(m, qd.z); m = fmaxf(m, qd.w);

    float obj  = sigmoidf(qa.x);
    float best = obj * sigmoidf(m);
    bool valid = (obj > CONF_THRES) && (best > CONF_THRES);
    float score = valid ? best : 0.0f;

    if (live) {
        if (valid) {
            unsigned bin = (__float_as_uint(score) - BIN_BASE) >> 14;
            atomicAdd(&g_hist[b * NBINS + bin], 1u);
        }
        unsigned long long key =
            ((unsigned long long)__float_as_uint(score) << 32) |
            (unsigned long long)(0xFFFFFFFFu - (unsigned)p);
        g_keys[(size_t)b * NPRED + p] = key;
    }
}

__global__ void score_kernel(const float* __restrict__ r0,
                             const float* __restrict__ r1,
                             const float* __restrict__ r2)
{
    int b  = blockIdx.y;
    int p0 = blockIdx.x * 512 + threadIdx.x;
    int p1 = p0 + 256;
    score_one(r0, r1, r2, b, p0, p0 < NPRED);
    score_one(r0, r1, r2, b, p1, p1 < NPRED);
}

// ---------------------------------------------------------------------------
// K2: radix-select + single bitonic sort + FUSED decode + hist re-zero
// ---------------------------------------------------------------------------
__device__ __forceinline__ void bitonic_sort_desc_1k(unsigned long long* a, int t)
{
    for (int k = 2; k <= 1024; k <<= 1) {
        for (int j = k >> 1; j > 0; j >>= 1) {
            int ixj = t ^ j;
            if (ixj > t) {
                unsigned long long u = a[t], w = a[ixj];
                bool desc = ((t & k) == 0);
                if ((u < w) == desc) { a[t] = w; a[ixj] = u; }
            }
            __syncthreads();
        }
    }
}

__device__ __forceinline__ void bitonic_merge_desc_1k(unsigned long long* a, int t)
{
    for (int j = 512; j > 0; j >>= 1) {
        int ixj = t ^ j;
        if (ixj > t) {
            unsigned long long u = a[t], w = a[ixj];
            if (u < w) { a[t] = w; a[ixj] = u; }
        }
        __syncthreads();
    }
}

__global__ __launch_bounds__(1024) void topk_decode_kernel(
    const float* __restrict__ r0,
    const float* __restrict__ r1,
    const float* __restrict__ r2,
    const float* __restrict__ stride,
    const float* __restrict__ ag)
{
    __shared__ unsigned long long sBuf[CAP];         // 32 KB
    __shared__ unsigned int sA[NBINS], sBn[NBINS];   // 8 KB scan ping-pong
    __shared__ int sCut, sCount;

    int b = blockIdx.x;
    int t = threadIdx.x;
    int lane = t & 31;
    const unsigned long long* k = g_keys + (size_t)b * NPRED;

    sA[t] = g_hist[b * NBINS + (NBINS - 1 - t)];
    if (t == 0) { sCut = 0; sCount = 0; }
    __syncthreads();

    unsigned int* src = sA;
    unsigned int* dst = sBn;
    for (int off = 1; off < NBINS; off <<= 1) {
        unsigned v = src[t] + ((t >= off) ? src[t - off] : 0u);
        dst[t] = v;
        __syncthreads();
        unsigned int* tmp = src; src = dst; dst = tmp;
    }
    {
        unsigned S     = src[NBINS - 1 - t];
        unsigned Snext = (t == NBINS - 1) ? 0u : src[NBINS - 2 - t];
        if (S >= TOPK && Snext < TOPK) sCut = t;
    }
    __syncthreads();
    int cutoff = sCut;
    unsigned long long thresh =
        ((unsigned long long)(BIN_BASE + ((unsigned)cutoff << 14))) << 32;

    // compact keys >= thresh (warp-aggregated atomic; order irrelevant pre-sort)
    const int NCHUNK = (NPRED + 1023) / 1024;   // 25
    for (int c = 0; c < NCHUNK; ++c) {
        int idx = c * 1024 + t;
        unsigned long long key = (idx < NPRED) ? k[idx] : 0ULL;
        bool pred = key >= thresh;
        unsigned m = __ballot_sync(0xffffffffu, pred);
        int nset = __popc(m);
        int basepos = 0;
        if (lane == 0 && nset) basepos = atomicAdd(&sCount, nset);
        basepos = __shfl_sync(0xffffffffu, basepos, 0);
        int pos = basepos + __popc(m & ((1u << lane) - 1u));
        if (pred && pos < CAP) sBuf[pos] = key;
    }
    __syncthreads();
    int n = sCount;

    if (n <= CAP) {
        int P = TOPK;
        while (P < n) P <<= 1;
        for (int i = t; i < P; i += 1024)
            if (i >= n) sBuf[i] = 0ULL;
        __syncthreads();

        int E = P >> 10;
        for (int kk = 2; kk <= P; kk <<= 1) {
            for (int j = kk >> 1; j > 0; j >>= 1) {
                for (int e = 0; e < E; ++e) {
                    int i = e * 1024 + t;
                    int ixj = i ^ j;
                    if (ixj > i) {
                        unsigned long long u = sBuf[i], w = sBuf[ixj];
                        bool desc = ((i & kk) == 0);
                        if ((u < w) == desc) { sBuf[i] = w; sBuf[ixj] = u; }
                    }
                }
                __syncthreads();
            }
        }
    } else {
        // fallback (never expected): exhaustive chunked merge top-k into sBuf
        unsigned long long* sTop = sBuf;
        unsigned long long* sCh  = sBuf + 1024;
        sTop[t] = k[t];
        __syncthreads();
        bitonic_sort_desc_1k(sTop, t);
        for (int c = 1; c < NCHUNK; ++c) {
            int idx = c * 1024 + t;
            sCh[t] = (idx < NPRED) ? k[idx] : 0ULL;
            __syncthreads();
            bitonic_sort_desc_1k(sCh, t);
            unsigned long long a = sTop[t];
            unsigned long long w = sCh[1023 - t];
            unsigned long long m = (a > w) ? a : w;
            __syncthreads();
            sTop[t] = m;
            __syncthreads();
            bitonic_merge_desc_1k(sTop, t);
        }
    }

    // ---- fused decode of the sorted top-1024 ----
    unsigned long long key = sBuf[t];
    float sc = __uint_as_float((unsigned)(key >> 32));
    unsigned p = 0xFFFFFFFFu - (unsigned)(key & 0xFFFFFFFFu);
    if (p >= NPRED) p = 0;   // zero-padded keys

    const float* v;
    float s;
    int scale, a, gy, gx;
    if (p < 19200) {
        scale = 0; int l = p;
        a = l / 6400; int r = l - a * 6400; gy = r / 80; gx = r - gy * 80;
        v = r0 + (size_t)(b * 19200 + l) * 20; s = stride[0];
    } else if (p < 24000) {
        scale = 1; int l = p - 19200;
        a = l / 1600; int r = l - a * 1600; gy = r / 40; gx = r - gy * 40;
        v = r1 + (size_t)(b * 4800 + l) * 20; s = stride[1];
    } else {
        scale = 2; int l = p - 24000;
        a = l / 400; int r = l - a * 400; gy = r / 20; gx = r - gy * 20;
        v = r2 + (size_t)(b * 1200 + l) * 20; s = stride[2];
    }

    const float4* v4 = (const float4*)v;
    float4 q0 = v4[0];
    float4 qa = v4[1];
    float4 qb = v4[2];
    float4 qc = v4[3];
    float4 qd = v4[4];

    float s0 = sigmoidf(q0.x);
    float s1 = sigmoidf(q0.y);
    float s2 = sigmoidf(q0.z);
    float s3 = sigmoidf(q0.w);
    float cx = (s0 * 2.0f - 0.5f + (float)gx) * s;
    float cy = (s1 * 2.0f - 0.5f + (float)gy) * s;
    float tw = s2 * 2.0f;
    float th = s3 * 2.0f;
    float w = tw * tw * ag[scale * 6 + a * 2 + 0];
    float h = th * th * ag[scale * 6 + a * 2 + 1];

    float x1 = cx - w * 0.5f;
    float y1 = cy - h * 0.5f;
    float x2 = cx + w * 0.5f;
    float y2 = cy + h * 0.5f;

    float cls[15] = { qa.y, qa.z, qa.w, qb.x, qb.y, qb.z, qb.w,
                      qc.x, qc.y, qc.z, qc.w, qd.x, qd.y, qd.z, qd.w };
    float mv = cls[0]; int mc = 0;
#pragma unroll
    for (int c = 1; c < 15; ++c)
        if (cls[c] > mv) { mv = cls[c]; mc = c; }

    int g = b * TOPK + t;
    g_box[g] = make_float4(x1, y1, x2, y2);
    g_bar[g] = (x2 - x1) * (y2 - y1);
    g_bsc[g] = sc; g_bcl[g] = (float)mc;

    int act = (sc > CONF_THRES) ? 1 : 0;
    unsigned ballot = __ballot_sync(0xffffffffu, act);
    if (lane == 0) g_active[b * 32 + (t >> 5)] = ballot;

    // ---- re-zero histogram for the next call (last reader of g_hist) ----
    g_hist[b * NBINS + t] = 0u;
}

// ---------------------------------------------------------------------------
// K3b: suppression bitmatrix — warp = row-group, word uniform per warp
// ---------------------------------------------------------------------------
__global__ __launch_bounds__(1024) void mask_kernel()
{
    __shared__ float4 sbox[TOPK];
    __shared__ float  sar[TOPK];

    int b = blockIdx.y;
    int x = blockIdx.x;          // 0..3 word-range split
    int t = threadIdx.x;
    int lane = t & 31, w_id = t >> 5;
    int base = b * TOPK;

    sbox[t] = g_box[base + t];
    sar[t]  = g_bar[base + t];
    __syncthreads();

    // balanced group map: SMSP s gets groups {s,7-s,8+s,15-s,16+s,23-s,24+s,31-s}
    int s = w_id & 3, q = w_id >> 2;
    int g = 8 * (q >> 1) + ((q & 1) ? (7 - s) : s);

    int i = g * 32 + lane;
    float4 bi = sbox[i];
    float ba = sar[i];

    int cnt = 32 - g;
    int wlo = g + (cnt * x) / 4;
    int whi = g + (cnt * (x + 1)) / 4;

    for (int w = wlo; w < whi; ++w) {
        unsigned bits = 0;
#pragma unroll
        for (int jj = 0; jj < 32; ++jj) {
            int j = (w << 5) + jj;            // uniform across lanes -> broadcast
            float4 bj = sbox[j];
            float aj = sar[j];
            float lx = fmaxf(bi.x, bj.x);
            float ly = fmaxf(bi.y, bj.y);
            float rx = fminf(bi.z, bj.z);
            float ry = fminf(bi.w, bj.w);
            float iw = fmaxf(rx - lx, 0.0f);
            float ih = fmaxf(ry - ly, 0.0f);
            float inter = iw * ih;
            // iou > T  <=>  inter > T * U   (U > 0 always)
            float U = ba + aj;
            U = U - inter;
            U = U + 1e-7f;
            if (inter > IOU_THRES * U) bits |= (1u << jj);
        }
        if (w == g) bits &= ~((2u << lane) - 1u);   // keep only j > i
        g_mask[(((size_t)(b * 32 + w)) << 10) + i] = bits;   // coalesced
    }
}

// ---------------------------------------------------------------------------
// K3c: fused greedy — 512 threads (128-reg budget: no spills), smem-staged
// bitmatrix, branchless double-buffered register resolve.
// smem layout: smask[i * 33 + w] (padded; conflict-free STS/LDS)
// ---------------------------------------------------------------------------
#define GREEDY_NT 512

__global__ __launch_bounds__(GREEDY_NT) void greedy_out_kernel(float* __restrict__ out)
{
    extern __shared__ unsigned smask[];              // 1024*33 words = 132 KB
    __shared__ unsigned s_keepw[32];
    __shared__ int s_woff[32];

    int b = blockIdx.x;
    int t = threadIdx.x;
    int lane = t & 31, wid = t >> 5;   // wid 0..15

    // stage: warp wid loads word-columns wid and wid+16 (coalesced LDG,
    // conflict-free STS: bank = (i + w) % 32)
    {
#pragma unroll
        for (int wq = 0; wq < 2; ++wq) {
            int w = wid + wq * 16;
            const unsigned* src = g_mask + (((size_t)(b * 32 + w)) << 10);
            for (int i = lane; i < TOPK; i += 32)
                smask[i * 33 + w] = src[i];
        }
    }
    __syncthreads();

    if (wid == 0) {
        unsigned activew = g_active[b * 32 + lane];
        unsigned removed = 0;
        unsigned wcA[32], wcB[32];

#pragma unroll
        for (int ii = 0; ii < 32; ++ii)
            wcA[ii] = smask[ii * 33 + lane];          // group 0

#pragma unroll 1
        for (int g = 0; g < 32; ++g) {
            // prefetch next group's column words (off the serial chain)
#pragma unroll
            for (int ii = 0; ii < 32; ++ii)
                wcB[ii] = (g < 31) ? smask[((g + 1) * 32 + ii) * 33 + lane] : 0u;

            unsigned keptm = 0;
            if (lane == g) {
                unsigned rem = removed;
#pragma unroll
                for (int ii = 0; ii < 32; ++ii) {
                    unsigned k = activew & ~rem & (1u << ii);        // LOP3
                    unsigned full = (unsigned)(0 - (int)(k >> ii));  // SHF+IADD
                    rem |= wcA[ii] & full;                           // LOP3
                    keptm |= k;
                }
                removed = rem;
                s_keepw[g] = keptm;
            }
            keptm = __shfl_sync(0xffffffffu, keptm, g);

            if (lane > g) {
                unsigned acc = 0;
#pragma unroll
                for (int ii = 0; ii < 32; ++ii)
                    acc |= wcA[ii] & (unsigned)(0 - (int)((keptm >> ii) & 1u));
                removed |= acc;
            }
#pragma unroll
            for (int ii = 0; ii < 32; ++ii) wcA[ii] = wcB[ii];
        }
    }
    __syncthreads();

    if (t == 0) {
        int acc = 0;
        for (int w = 0; w < 32; ++w) { s_woff[w] = acc; acc += __popc(s_keepw[w]); }
    }
    __syncthreads();

    float* outB = out + (size_t)b * MAXDET * 6;
    for (int q = t; q < MAXDET * 6; q += GREEDY_NT) outB[q] = 0.0f;
    __syncthreads();

#pragma unroll
    for (int cq = 0; cq < 2; ++cq) {
        int c = t + cq * GREEDY_NT;                   // candidate index 0..1023
        int cw = c >> 5, cl = c & 31;
        int keepme = (s_keepw[cw] >> cl) & 1;
        int rank = s_woff[cw] + __popc(s_keepw[cw] & ((1u << cl) - 1u));
        if (keepme && rank < MAXDET) {
            int g = b * TOPK + c;
            float4 bx = g_box[g];
            float* r = outB + rank * 6;
            r[0] = bx.x; r[1] = bx.y; r[2] = bx.z; r[3] = bx.w;
            r[4] = g_bsc[g]; r[5] = g_bcl[g];
        }
    }
}

// ---------------------------------------------------------------------------
extern "C" void kernel_launch(void* const* d_in, const int* in_sizes, int n_in,
                              void* d_out, int out_size)
{
    const float* r0 = (const float*)d_in[0];
    const float* r1 = (const float*)d_in[1];
    const float* r2 = (const float*)d_in[2];
    const float* stride = (const float*)d_in[3];
    const float* ag = (const float*)d_in[4];
    float* out = (float*)d_out;

    const int MASK_SMEM = TOPK * 33 * (int)sizeof(unsigned);   // 135168 B
    cudaFuncSetAttribute(greedy_out_kernel,
                         cudaFuncAttributeMaxDynamicSharedMemorySize, MASK_SMEM);

    score_kernel<<<dim3((NPRED + 511) / 512, B), 256>>>(r0, r1, r2);
    topk_decode_kernel<<<B, 1024>>>(r0, r1, r2, stride, ag);
    mask_kernel<<<dim3(4, B), 1024>>>();
    greedy_out_kernel<<<B, GREEDY_NT, MASK_SMEM>>>(out);
}

// round 17
// speedup vs baseline: 1.1724x; 1.1724x over previous
#include <cuda_runtime.h>
#include <cstdint>

#define B 64
#define NPRED 25200          // 3*(6400+1600+400) anchors*cells
#define TOPK 1024
#define MAXDET 300
#define CONF_THRES 0.25f
#define IOU_THRES 0.45f
#define NBINS 1024
#define CAP 4096             // smem candidate buffer (keys >= bin threshold)

// valid scores lie in (0.25, 1): fp32 bits in (0x3E800000, 0x3F800000)
#define BIN_BASE 0x3E800000u

__device__ unsigned long long g_keys[B * NPRED];   // (score_bits<<32)|(~idx)
__device__ unsigned int       g_hist[B * NBINS];   // zero-init; re-zeroed by K2 tail

// candidate data (decoded boxes for the 1024 selected per image)
__device__ float4 g_box[B * TOPK];                 // x1,y1,x2,y2
__device__ float  g_bar[B * TOPK];
__device__ float  g_bsc[B * TOPK];
__device__ float  g_bcl[B * TOPK];
__device__ unsigned g_active[B * 32];

// suppression bitmatrix, WORD-MAJOR: g_mask[b][w][i] bit jj -> row i suppresses
// j = w*32+jj (j>i bits only). Words w < i/32 are never written (stay 0) and
// only ever OR-ed (harmless).
__device__ unsigned g_mask[B * 32 * TOPK];         // 8.4 MB

__device__ __forceinline__ float sigmoidf(float x) {
    return 1.0f / (1.0f + expf(-x));
}

// ---------------------------------------------------------------------------
// K1: per-candidate score -> sortable key + score-bin histogram
// ---------------------------------------------------------------------------
__device__ __forceinline__ void score_one(const float* __restrict__ r0,
                                          const float* __restrict__ r1,
                                          const float* __restrict__ r2,
                                          int b, int p, bool live)
{
    int pc = p < NPRED ? p : NPRED - 1;
    const float* v;
    if (pc < 19200)      v = r0 + (size_t)(b * 19200 + pc) * 20;
    else if (pc < 24000) v = r1 + (size_t)(b * 4800 + (pc - 19200)) * 20;
    else                 v = r2 + (size_t)(b * 1200 + (pc - 24000)) * 20;

    const float4* v4 = (const float4*)v;
    float4 qa = v4[1];   // obj, cls0..2
    float4 qb = v4[2];
    float4 qc = v4[3];
    float4 qd = v4[4];

    float m = qa.y;
    m = fmaxf(m, qa.z); m = fmaxf(m, qa.w);
    m = fmaxf(m, qb.x); m = fmaxf(m, qb.y); m = fmaxf(m, qb.z); m = fmaxf(m, qb.w);
    m = fmaxf(m, qc.x); m = fmaxf(m, qc.y); m = fmaxf(m, qc.z); m = fmaxf(m, qc.w);
    m = fmaxf(m, qd.x); m = fmaxf(m, qd.y); m = fmaxf(m, qd.z); m = fmaxf(m, qd.w);

    float obj  = sigmoidf(qa.x);
    float best = obj * sigmoidf(m);
    bool valid = (obj > CONF_THRES) && (best > CONF_THRES);
    float score = valid ? best : 0.0f;

    if (live) {
        if (valid) {
            unsigned bin = (__float_as_uint(score) - BIN_BASE) >> 14;
            atomicAdd(&g_hist[b * NBINS + bin], 1u);
        }
        unsigned long long key =
            ((unsigned long long)__float_as_uint(score) << 32) |
            (unsigned long long)(0xFFFFFFFFu - (unsigned)p);
        g_keys[(size_t)b * NPRED + p] = key;
    }
}

__global__ void score_kernel(const float* __restrict__ r0,
                             const float* __restrict__ r1,
                             const float* __restrict__ r2)
{
    int b  = blockIdx.y;
    int p0 = blockIdx.x * 512 + threadIdx.x;
    int p1 = p0 + 256;
    score_one(r0, r1, r2, b, p0, p0 < NPRED);
    score_one(r0, r1, r2, b, p1, p1 < NPRED);
}

// ---------------------------------------------------------------------------
// K2: radix-select + single bitonic sort + FUSED decode + hist re-zero
// ---------------------------------------------------------------------------
__device__ __forceinline__ void bitonic_sort_desc_1k(unsigned long long* a, int t)
{
    for (int k = 2; k <= 1024; k <<= 1) {
        for (int j = k >> 1; j > 0; j >>= 1) {
            int ixj = t ^ j;
            if (ixj > t) {
                unsigned long long u = a[t], w = a[ixj];
                bool desc = ((t & k) == 0);
                if ((u < w) == desc) { a[t] = w; a[ixj] = u; }
            }
            __syncthreads();
        }
    }
}

__device__ __forceinline__ void bitonic_merge_desc_1k(unsigned long long* a, int t)
{
    for (int j = 512; j > 0; j >>= 1) {
        int ixj = t ^ j;
        if (ixj > t) {
            unsigned long long u = a[t], w = a[ixj];
            if (u < w) { a[t] = w; a[ixj] = u; }
        }
        __syncthreads();
    }
}

__global__ __launch_bounds__(1024) void topk_decode_kernel(
    const float* __restrict__ r0,
    const float* __restrict__ r1,
    const float* __restrict__ r2,
    const float* __restrict__ stride,
    const float* __restrict__ ag)
{
    __shared__ unsigned long long sBuf[CAP];         // 32 KB
    __shared__ unsigned int sA[NBINS], sBn[NBINS];   // 8 KB scan ping-pong
    __shared__ int sCut, sCount;

    int b = blockIdx.x;
    int t = threadIdx.x;
    int lane = t & 31;
    const unsigned long long* k = g_keys + (size_t)b * NPRED;

    sA[t] = g_hist[b * NBINS + (NBINS - 1 - t)];
    if (t == 0) { sCut = 0; sCount = 0; }
    __syncthreads();

    unsigned int* src = sA;
    unsigned int* dst = sBn;
    for (int off = 1; off < NBINS; off <<= 1) {
        unsigned v = src[t] + ((t >= off) ? src[t - off] : 0u);
        dst[t] = v;
        __syncthreads();
        unsigned int* tmp = src; src = dst; dst = tmp;
    }
    {
        unsigned S     = src[NBINS - 1 - t];
        unsigned Snext = (t == NBINS - 1) ? 0u : src[NBINS - 2 - t];
        if (S >= TOPK && Snext < TOPK) sCut = t;
    }
    __syncthreads();
    int cutoff = sCut;
    unsigned long long thresh =
        ((unsigned long long)(BIN_BASE + ((unsigned)cutoff << 14))) << 32;

    // compact keys >= thresh (warp-aggregated atomic; order irrelevant pre-sort)
    const int NCHUNK = (NPRED + 1023) / 1024;   // 25
    for (int c = 0; c < NCHUNK; ++c) {
        int idx = c * 1024 + t;
        unsigned long long key = (idx < NPRED) ? k[idx] : 0ULL;
        bool pred = key >= thresh;
        unsigned m = __ballot_sync(0xffffffffu, pred);
        int nset = __popc(m);
        int basepos = 0;
        if (lane == 0 && nset) basepos = atomicAdd(&sCount, nset);
        basepos = __shfl_sync(0xffffffffu, basepos, 0);
        int pos = basepos + __popc(m & ((1u << lane) - 1u));
        if (pred && pos < CAP) sBuf[pos] = key;
    }
    __syncthreads();
    int n = sCount;

    if (n <= CAP) {
        int P = TOPK;
        while (P < n) P <<= 1;
        for (int i = t; i < P; i += 1024)
            if (i >= n) sBuf[i] = 0ULL;
        __syncthreads();

        int E = P >> 10;
        for (int kk = 2; kk <= P; kk <<= 1) {
            for (int j = kk >> 1; j > 0; j >>= 1) {
                for (int e = 0; e < E; ++e) {
                    int i = e * 1024 + t;
                    int ixj = i ^ j;
                    if (ixj > i) {
                        unsigned long long u = sBuf[i], w = sBuf[ixj];
                        bool desc = ((i & kk) == 0);
                        if ((u < w) == desc) { sBuf[i] = w; sBuf[ixj] = u; }
                    }
                }
                __syncthreads();
            }
        }
    } else {
        // fallback (never expected): exhaustive chunked merge top-k into sBuf
        unsigned long long* sTop = sBuf;
        unsigned long long* sCh  = sBuf + 1024;
        sTop[t] = k[t];
        __syncthreads();
        bitonic_sort_desc_1k(sTop, t);
        for (int c = 1; c < NCHUNK; ++c) {
            int idx = c * 1024 + t;
            sCh[t] = (idx < NPRED) ? k[idx] : 0ULL;
            __syncthreads();
            bitonic_sort_desc_1k(sCh, t);
            unsigned long long a = sTop[t];
            unsigned long long w = sCh[1023 - t];
            unsigned long long m = (a > w) ? a : w;
            __syncthreads();
            sTop[t] = m;
            __syncthreads();
            bitonic_merge_desc_1k(sTop, t);
        }
    }

    // ---- fused decode of the sorted top-1024 ----
    unsigned long long key = sBuf[t];
    float sc = __uint_as_float((unsigned)(key >> 32));
    unsigned p = 0xFFFFFFFFu - (unsigned)(key & 0xFFFFFFFFu);
    if (p >= NPRED) p = 0;   // zero-padded keys

    const float* v;
    float s;
    int scale, a, gy, gx;
    if (p < 19200) {
        scale = 0; int l = p;
        a = l / 6400; int r = l - a * 6400; gy = r / 80; gx = r - gy * 80;
        v = r0 + (size_t)(b * 19200 + l) * 20; s = stride[0];
    } else if (p < 24000) {
        scale = 1; int l = p - 19200;
        a = l / 1600; int r = l - a * 1600; gy = r / 40; gx = r - gy * 40;
        v = r1 + (size_t)(b * 4800 + l) * 20; s = stride[1];
    } else {
        scale = 2; int l = p - 24000;
        a = l / 400; int r = l - a * 400; gy = r / 20; gx = r - gy * 20;
        v = r2 + (size_t)(b * 1200 + l) * 20; s = stride[2];
    }

    const float4* v4 = (const float4*)v;
    float4 q0 = v4[0];
    float4 qa = v4[1];
    float4 qb = v4[2];
    float4 qc = v4[3];
    float4 qd = v4[4];

    float s0 = sigmoidf(q0.x);
    float s1 = sigmoidf(q0.y);
    float s2 = sigmoidf(q0.z);
    float s3 = sigmoidf(q0.w);
    float cx = (s0 * 2.0f - 0.5f + (float)gx) * s;
    float cy = (s1 * 2.0f - 0.5f + (float)gy) * s;
    float tw = s2 * 2.0f;
    float th = s3 * 2.0f;
    float w = tw * tw * ag[scale * 6 + a * 2 + 0];
    float h = th * th * ag[scale * 6 + a * 2 + 1];

    float x1 = cx - w * 0.5f;
    float y1 = cy - h * 0.5f;
    float x2 = cx + w * 0.5f;
    float y2 = cy + h * 0.5f;

    float cls[15] = { qa.y, qa.z, qa.w, qb.x, qb.y, qb.z, qb.w,
                      qc.x, qc.y, qc.z, qc.w, qd.x, qd.y, qd.z, qd.w };
    float mv = cls[0]; int mc = 0;
#pragma unroll
    for (int c = 1; c < 15; ++c)
        if (cls[c] > mv) { mv = cls[c]; mc = c; }

    int g = b * TOPK + t;
    g_box[g] = make_float4(x1, y1, x2, y2);
    g_bar[g] = (x2 - x1) * (y2 - y1);
    g_bsc[g] = sc; g_bcl[g] = (float)mc;

    int act = (sc > CONF_THRES) ? 1 : 0;
    unsigned ballot = __ballot_sync(0xffffffffu, act);
    if (lane == 0) g_active[b * 32 + (t >> 5)] = ballot;

    // ---- re-zero histogram for the next call (last reader of g_hist) ----
    g_hist[b * NBINS + t] = 0u;
}

// ---------------------------------------------------------------------------
// K3b: suppression bitmatrix — warp = row-group, word uniform per warp
// ---------------------------------------------------------------------------
__global__ __launch_bounds__(1024) void mask_kernel()
{
    __shared__ float4 sbox[TOPK];
    __shared__ float  sar[TOPK];

    int b = blockIdx.y;
    int x = blockIdx.x;          // 0..3 word-range split
    int t = threadIdx.x;
    int lane = t & 31, w_id = t >> 5;
    int base = b * TOPK;

    sbox[t] = g_box[base + t];
    sar[t]  = g_bar[base + t];
    __syncthreads();

    // balanced group map: SMSP s gets groups {s,7-s,8+s,15-s,16+s,23-s,24+s,31-s}
    int s = w_id & 3, q = w_id >> 2;
    int g = 8 * (q >> 1) + ((q & 1) ? (7 - s) : s);

    int i = g * 32 + lane;
    float4 bi = sbox[i];
    float ba = sar[i];

    int cnt = 32 - g;
    int wlo = g + (cnt * x) / 4;
    int whi = g + (cnt * (x + 1)) / 4;

    for (int w = wlo; w < whi; ++w) {
        unsigned bits = 0;
#pragma unroll
        for (int jj = 0; jj < 32; ++jj) {
            int j = (w << 5) + jj;            // uniform across lanes -> broadcast
            float4 bj = sbox[j];
            float aj = sar[j];
            float lx = fmaxf(bi.x, bj.x);
            float ly = fmaxf(bi.y, bj.y);
            float rx = fminf(bi.z, bj.z);
            float ry = fminf(bi.w, bj.w);
            float iw = fmaxf(rx - lx, 0.0f);
            float ih = fmaxf(ry - ly, 0.0f);
            float inter = iw * ih;
            // iou > T  <=>  inter > T * U   (U > 0 always)
            float U = ba + aj;
            U = U - inter;
            U = U + 1e-7f;
            if (inter > IOU_THRES * U) bits |= (1u << jj);
        }
        if (w == g) bits &= ~((2u << lane) - 1u);   // keep only j > i
        g_mask[(((size_t)(b * 32 + w)) << 10) + i] = bits;   // coalesced
    }
}

// ---------------------------------------------------------------------------
// K3c: fixed-point parallel NMS + output (1024 threads, no register arrays)
// Greedy keep is the unique fixed point of
//   k[j] = active[j] & ~OR_{i<j}(k[i] & M[i][j]);
// iterate k <- F(k) from k=active; break at fixed point (= exact greedy).
// smem layout: smask[i * 33 + w] (padded; conflict-free STS/LDS)
// ---------------------------------------------------------------------------
__global__ __launch_bounds__(1024) void greedy_out_kernel(float* __restrict__ out)
{
    extern __shared__ unsigned smask[];              // 1024*33 words = 132 KB
    __shared__ unsigned s_part[32 * 33];             // per-group partial ORs
    __shared__ unsigned s_keepw[32];
    __shared__ unsigned s_activew[32];
    __shared__ int s_changed;
    __shared__ int s_woff[32];

    int b = blockIdx.x;
    int t = threadIdx.x;
    int lane = t & 31, wid = t >> 5;

    // stage: warp wid loads suppression word wid for all rows (coalesced LDG,
    // conflict-free STS: bank = (i + wid) % 32)
    {
        const unsigned* src = g_mask + (((size_t)(b * 32 + wid)) << 10);
        for (int i = lane; i < TOPK; i += 32)
            smask[i * 33 + wid] = src[i];
    }
    if (t < 32) {
        unsigned aw = g_active[b * 32 + t];
        s_activew[t] = aw;
        s_keepw[t] = aw;             // k^0 = active
    }
    if (t == 0) s_changed = 0;
    __syncthreads();

    for (int iter = 0; iter < TOPK; ++iter) {
        // stage 1: warp 'wid' ORs suppression words of its kept rows;
        // lane holds word index: partial[wid][lane]
        unsigned keptw = s_keepw[wid];
        unsigned acc = 0;
#pragma unroll
        for (int ii = 0; ii < 32; ++ii) {
            unsigned full = (unsigned)(0 - (int)((keptw >> ii) & 1u));
            acc |= smask[(wid * 32 + ii) * 33 + lane] & full;
        }
        s_part[wid * 33 + lane] = acc;
        __syncthreads();

        // stage 2: warp 'wid' combines word 'wid' across the 32 groups
        unsigned v = s_part[lane * 33 + wid];
        v = __reduce_or_sync(0xffffffffu, v);        // removed word 'wid'
        unsigned newk = s_activew[wid] & ~v;
        if (lane == 0) {
            if (newk != s_keepw[wid]) { s_keepw[wid] = newk; s_changed = 1; }
        }
        __syncthreads();

        int changed = s_changed;
        __syncthreads();
        if (t == 0) s_changed = 0;
        if (!changed) break;                          // fixed point == greedy
    }
    __syncthreads();

    if (t == 0) {
        int acc = 0;
        for (int w = 0; w < 32; ++w) { s_woff[w] = acc; acc += __popc(s_keepw[w]); }
    }
    __syncthreads();

    int keepme = (s_keepw[wid] >> lane) & 1;
    int rank = s_woff[wid] + __popc(s_keepw[wid] & ((1u << lane) - 1u));

    float* outB = out + (size_t)b * MAXDET * 6;
    for (int q = t; q < MAXDET * 6; q += 1024) outB[q] = 0.0f;
    __syncthreads();

    if (keepme && rank < MAXDET) {
        int g = b * TOPK + t;
        float4 bx = g_box[g];
        float* r = outB + rank * 6;
        r[0] = bx.x; r[1] = bx.y; r[2] = bx.z; r[3] = bx.w;
        r[4] = g_bsc[g]; r[5] = g_bcl[g];
    }
}

// ---------------------------------------------------------------------------
extern "C" void kernel_launch(void* const* d_in, const int* in_sizes, int n_in,
                              void* d_out, int out_size)
{
    const float* r0 = (const float*)d_in[0];
    const float* r1 = (const float*)d_in[1];
    const float* r2 = (const float*)d_in[2];
    const float* stride = (const float*)d_in[3];
    const float* ag = (const float*)d_in[4];
    float* out = (float*)d_out;

    const int MASK_SMEM = TOPK * 33 * (int)sizeof(unsigned);   // 135168 B
    cudaFuncSetAttribute(greedy_out_kernel,
                         cudaFuncAttributeMaxDynamicSharedMemorySize, MASK_SMEM);

    score_kernel<<<dim3((NPRED + 511) / 512, B), 256>>>(r0, r1, r2);
    topk_decode_kernel<<<B, 1024>>>(r0, r1, r2, stride, ag);
    mask_kernel<<<dim3(4, B), 1024>>>();
    greedy_out_kernel<<<B, 1024, MASK_SMEM>>>(out);
}